// round 16
// baseline (speedup 1.0000x reference)
#include <cuda_runtime.h>
#include <cuda_bf16.h>
#include <cuda_fp16.h>
#include <stdint.h>
#include <math.h>

// ---------------- problem constants ----------------
#define NB    2
#define DD    256
#define LQT   12240
#define NHH   8
#define NLAY  6
#define DFF_  1024
#define MTOT  (NB*LQT)   // 24480

__constant__ int c_H[4]     = {96,48,24,12};
__constant__ int c_W[4]     = {96,48,24,12};
__constant__ int c_start[4] = {0,9216,11520,12096};
__constant__ int c_len[4]   = {9216,2304,576,144};
__constant__ int c_cin[4]   = {256,512,768,1024};

// ---------------- scratch (device globals; no allocation) ----------------
__device__ float g_src[NB*LQT*DD];
__device__ float g_pos[NB*LQT*DD];
__device__ float g_off[NB*LQT*DD];
__device__ float g_aw [NB*LQT*128];
__device__ float g_val[NB*LQT*DD];    // fp16 payload
__device__ float g_att[NB*LQT*DD];
__device__ float g_ref[LQT*2];
__device__ float g_cbias[NLAY*384];
// fp16 hi/lo activation buffers (GEMM A-side inputs)
__device__ __half g_qh [MTOT*DD],  g_ql [MTOT*DD];
__device__ __half g_sh [MTOT*DD],  g_sl [MTOT*DD];
__device__ __half g_th [MTOT*DD],  g_tl [MTOT*DD];
__device__ __half g_msh[MTOT*DD],  g_msl[MTOT*DD];
__device__ __half g_hbh[MTOT*DFF_], g_hbl[MTOT*DFF_];

// fp16 weights; oaw fused per layer: off(65536)+aw(32768)
#define OFF_OAW 0
#define OFF_VAL 589824
#define OFF_OUT 983040
#define OFF_L1  1376256
#define OFF_L2  2949120
#define W_TOTAL 4521984
__device__ __half g_wf[W_TOTAL];

__device__ __forceinline__ int lvl_of(int q) {
    return (q < 9216) ? 0 : (q < 11520) ? 1 : (q < 12096) ? 2 : 3;
}

__device__ __forceinline__ float blockSum(float v) {
    __shared__ float sh[8];
    int lane = threadIdx.x & 31, w = threadIdx.x >> 5;
    #pragma unroll
    for (int o = 16; o > 0; o >>= 1) v += __shfl_xor_sync(0xffffffffu, v, o);
    if (lane == 0) sh[w] = v;
    __syncthreads();
    if (w == 0) {
        float r = (lane < 8) ? sh[lane] : 0.f;
        #pragma unroll
        for (int o = 4; o > 0; o >>= 1) r += __shfl_xor_sync(0xffffffffu, r, o);
        if (lane == 0) sh[0] = r;
    }
    __syncthreads();
    float res = sh[0];
    __syncthreads();
    return res;
}

__device__ __forceinline__ void split2h(float x, __half& h, __half& l) {
    h = __float2half_rn(x);
    l = __float2half_rn(x - __half2float(h));
}

// ---------------- launch 0: weight convert + concat bias + pos/ref ----------------
#define N_WB (W_TOTAL + NLAY*384)
__global__ void setup_kernel(
    const float* __restrict__ off_w, const float* __restrict__ aw_w,
    const float* __restrict__ val_w, const float* __restrict__ out_w,
    const float* __restrict__ l1_w,  const float* __restrict__ l2_w,
    const float* __restrict__ off_b, const float* __restrict__ aw_b,
    __half* __restrict__ wf, float* __restrict__ cbias,
    const float* __restrict__ lemb, float* __restrict__ pos, float* __restrict__ ref)
{
    int i = blockIdx.x*blockDim.x + threadIdx.x;
    if (i < W_TOTAL) {
        float x; long long o;
        if (i < 393216) {
            int l = i >> 16, r = i & 65535;
            x = off_w[i]; o = (long long)l*98304 + r;
        } else if (i < 589824) {
            int j = i - 393216;
            int l = j >> 15, r = j & 32767;
            x = aw_w[j]; o = (long long)l*98304 + 65536 + r;
        } else if (i < 983040) {
            x = val_w[i - 589824]; o = i;
        } else if (i < 1376256) {
            x = out_w[i - 983040]; o = i;
        } else if (i < 2949120) {
            x = l1_w[i - 1376256]; o = i;
        } else {
            x = l2_w[i - 2949120]; o = i;
        }
        wf[o] = __float2half_rn(x);
        return;
    }
    if (i < N_WB) {
        int j = i - W_TOTAL;
        int l = j / 384, c = j % 384;
        cbias[j] = (c < 256) ? off_b[l*256 + c] : aw_b[l*128 + (c - 256)];
        return;
    }
    int idx = i - N_WB;
    if (idx >= LQT*DD) return;
    int qq = idx >> 8, d = idx & 255;
    int lvl = lvl_of(qq);
    int st = c_start[lvl], H = c_H[lvl], W = c_W[lvl];
    int p = qq - st; int y = p / W, x = p % W;
    const float TWO_PI = 6.28318530717958647692f;
    const float LN1E4_64 = 0.14391156831212787f;
    float v;
    if (d < 128) {
        float e = (float)(y+1) / ((float)H + 1e-6f) * TWO_PI;
        int k = d >> 1;
        float u = e * expf(-LN1E4_64 * (float)k);
        v = (d & 1) ? cosf(u) : sinf(u);
    } else {
        int dd = d - 128;
        float e = (float)(x+1) / ((float)W + 1e-6f) * TWO_PI;
        int k = dd >> 1;
        float u = e * expf(-LN1E4_64 * (float)k);
        v = (dd & 1) ? cosf(u) : sinf(u);
    }
    v += lemb[lvl*DD + d];
    pos[(size_t)qq*DD + d] = v;
    pos[(size_t)(LQT + qq)*DD + d] = v;
    if (d == 0) {
        ref[qq*2+0] = ((float)x + 0.5f) / (float)W;
        ref[qq*2+1] = ((float)y + 0.5f) / (float)H;
    }
}

// ---------------- launch 1: tokenizer (all levels/batches) ----------------
__global__ void __launch_bounds__(256)
tokenizer_kernel(const float* __restrict__ X0, const float* __restrict__ X1,
                 const float* __restrict__ X2, const float* __restrict__ X3,
                 const float* __restrict__ W0, const float* __restrict__ W1,
                 const float* __restrict__ W2, const float* __restrict__ W3,
                 const float* __restrict__ B0, const float* __restrict__ B1,
                 const float* __restrict__ B2, const float* __restrict__ B3,
                 float* __restrict__ src)
{
    int bid = blockIdx.x;
    int lvl, base;
    if      (bid < 1152) { lvl = 0; base = 0; }
    else if (bid < 1440) { lvl = 1; base = 1152; }
    else if (bid < 1512) { lvl = 2; base = 1440; }
    else                 { lvl = 3; base = 1512; }
    int HW = c_len[lvl], K = c_cin[lvl];
    int rem = bid - base;
    int span = ((HW + 63)/64) * 4;
    int b = rem / span; rem -= b*span;
    int m0 = (rem >> 2) * 64, n0 = (rem & 3) * 64;
    const float* A = (lvl==0?X0:lvl==1?X1:lvl==2?X2:X3) + (size_t)b*K*HW;
    const float* W = (lvl==0?W0:lvl==1?W1:lvl==2?W2:W3);
    const float* bias = (lvl==0?B0:lvl==1?B1:lvl==2?B2:B3);
    float* C = src + ((size_t)b*LQT + c_start[lvl]) * DD;
    int M = HW, N = DD;

    __shared__ __align__(16) float As[16][68];
    __shared__ __align__(16) float Ws[16][68];
    int tid = threadIdx.x;
    int tx = tid & 15, ty = tid >> 4;
    int ak = tid >> 4, amq = (tid & 15) * 4;
    int wn = tid >> 2, wk  = (tid & 3) * 4;
    bool aok = (m0 + amq) < M;
    float acc[4][4] = {};
    for (int k0 = 0; k0 < K; k0 += 16) {
        float4 a4 = aok ? *(const float4*)(A + (size_t)(k0+ak)*M + m0 + amq)
                        : make_float4(0.f,0.f,0.f,0.f);
        *(float4*)&As[ak][amq] = a4;
        float4 w4 = *(const float4*)(W + (size_t)(n0+wn)*K + k0 + wk);
        Ws[wk+0][wn]=w4.x; Ws[wk+1][wn]=w4.y; Ws[wk+2][wn]=w4.z; Ws[wk+3][wn]=w4.w;
        __syncthreads();
        #pragma unroll
        for (int k = 0; k < 16; k++) {
            float4 a = *(const float4*)&As[k][ty*4];
            float4 w = *(const float4*)&Ws[k][tx*4];
            float ar[4] = {a.x,a.y,a.z,a.w}, wr[4] = {w.x,w.y,w.z,w.w};
            #pragma unroll
            for (int i = 0; i < 4; i++)
                #pragma unroll
                for (int j = 0; j < 4; j++)
                    acc[i][j] = fmaf(ar[i], wr[j], acc[i][j]);
        }
        __syncthreads();
    }
    #pragma unroll
    for (int i = 0; i < 4; i++) {
        int m = m0 + ty*4 + i;
        if (m >= M) break;
        #pragma unroll
        for (int j = 0; j < 4; j++) {
            int n = n0 + tx*4 + j;
            C[(size_t)m*N + n] = acc[i][j] + bias[n];
        }
    }
}

// ---------------- launch 2: GroupNorm + prep splits (fused) ----------------
__global__ void __launch_bounds__(256)
gn_kernel(float* __restrict__ src, const float* __restrict__ g, const float* __restrict__ b,
          const float* __restrict__ pos,
          __half* __restrict__ sh_, __half* __restrict__ sl_,
          __half* __restrict__ qh_, __half* __restrict__ ql_)
{
    int grp = blockIdx.x & 31;
    int bb  = (blockIdx.x >> 5) & 1;
    int lvl = blockIdx.x >> 6;
    int L = c_len[lvl], st = c_start[lvl];
    size_t gbase = ((size_t)bb*LQT + st) * DD;
    float* base = src + gbase;
    int n = L * 8;
    float s = 0.f;
    for (int i = threadIdx.x; i < n; i += 256)
        s += base[(size_t)(i>>3)*DD + grp*8 + (i&7)];
    float mean = blockSum(s) / (float)n;
    float s2 = 0.f;
    for (int i = threadIdx.x; i < n; i += 256) {
        float d = base[(size_t)(i>>3)*DD + grp*8 + (i&7)] - mean;
        s2 += d*d;
    }
    float rstd = rsqrtf(blockSum(s2) / (float)n + 1e-5f);
    for (int i = threadIdx.x; i < n; i += 256) {
        int c = grp*8 + (i&7);
        size_t id = (size_t)(i>>3)*DD + c;
        float y = (base[id] - mean) * rstd * g[lvl*DD + c] + b[lvl*DD + c];
        base[id] = y;
        size_t gid = gbase + id;
        __half h, l;
        split2h(y, h, l);          sh_[gid] = h; sl_[gid] = l;
        split2h(y + pos[gid], h, l); qh_[gid] = h; ql_[gid] = l;
    }
}

// ---------------- fp16x2 cp.async tensor-core GEMM ----------------
// BM=64, BN=64, 256 thr (8 warps 2m x 4n, warp tile 32x16), BK=32, 3-stage.
// Stage layout: Ah(5120) Al(5120) B(5120) = 15360 B. 4 CTAs/SM.
// Dual-path merged GEMM via split_x. mode 0: fp32 out split at n_split;
// 1: fp16 out to C0; 2: fp16 hi/lo out to Oh/Ol.
#define STG_SZ 15360
#define SMEM_BB (3*STG_SZ)

__device__ __forceinline__ void mma_f16(float c[4], const unsigned a[4],
                                        unsigned b0, unsigned b1)
{
    asm volatile("mma.sync.aligned.m16n8k16.row.col.f32.f16.f16.f32 "
        "{%0,%1,%2,%3}, {%4,%5,%6,%7}, {%8,%9}, {%0,%1,%2,%3};"
        : "+f"(c[0]), "+f"(c[1]), "+f"(c[2]), "+f"(c[3])
        : "r"(a[0]), "r"(a[1]), "r"(a[2]), "r"(a[3]), "r"(b0), "r"(b1));
}
__device__ __forceinline__ void ldsm4(unsigned r[4], unsigned a) {
    asm volatile("ldmatrix.sync.aligned.m8n8.x4.shared.b16 {%0,%1,%2,%3}, [%4];"
        : "=r"(r[0]), "=r"(r[1]), "=r"(r[2]), "=r"(r[3]) : "r"(a));
}
__device__ __forceinline__ void cp16(unsigned dst, const void* src) {
    asm volatile("cp.async.cg.shared.global [%0], [%1], 16;" :: "r"(dst), "l"(src));
}
__device__ __forceinline__ void cp16z(unsigned dst, const void* src, int sz) {
    asm volatile("cp.async.cg.shared.global [%0], [%1], 16, %2;" :: "r"(dst), "l"(src), "r"(sz));
}
__device__ __forceinline__ void cp_commit() { asm volatile("cp.async.commit_group;"); }
__device__ __forceinline__ void cp_wait1()  { asm volatile("cp.async.wait_group 1;"); }
__device__ __forceinline__ void cp_wait0()  { asm volatile("cp.async.wait_group 0;"); }

__device__ __forceinline__ void fill_bb(
    const __half* __restrict__ Ah, const __half* __restrict__ Al,
    const __half* __restrict__ Wf,
    unsigned sbase, int stage, int m0, int n0, int t, int M, int K, int tid)
{
    int row = tid >> 2, seg = tid & 3;          // 64 rows x 4 16B-segments
    unsigned so = sbase + (unsigned)(stage*STG_SZ) + (unsigned)(row*80 + seg*16);
    size_t ga = (size_t)(m0 + row)*K + t*32 + seg*8;
    int asz = ((m0 + row) < M) ? 16 : 0;
    cp16z(so,         Ah + ga, asz);
    cp16z(so + 5120,  Al + ga, asz);
    size_t gb = (size_t)(n0 + row)*K + t*32 + seg*8;
    cp16 (so + 10240, Wf + gb);
    cp_commit();
}

__global__ void __launch_bounds__(256, 4)
gemm_bb_kernel(const __half* __restrict__ Ah0, const __half* __restrict__ Al0,
               const __half* __restrict__ Wf0, const float* __restrict__ bias0,
               float* __restrict__ C0, float* __restrict__ C1, int n_split,
               __half* __restrict__ Oh, __half* __restrict__ Ol,
               int M, int Ntot0, int K, int relu0, int mode0,
               int split_x,
               const __half* __restrict__ Ah2, const __half* __restrict__ Al2,
               const __half* __restrict__ Wf2, const float* __restrict__ bias2,
               float* __restrict__ C2, int Ntot2, int mode2)
{
    extern __shared__ __align__(16) char smem[];
    unsigned sbase = (unsigned)__cvta_generic_to_shared(smem);
    int tid  = threadIdx.x;
    int lane = tid & 31, warp = tid >> 5;
    int wm = warp & 1, wn = warp >> 1;          // 2(m) x 4(n), warp tile 32x16
    int bx = blockIdx.x;
    int m0 = blockIdx.y * 64;
    int g = lane >> 2, qd = lane & 3;
    const int NT = K / 32;

    const __half *Ah, *Al, *Wf; const float* bias;
    int n0, Ntot, relu, mode;
    float* Cm;
    if (bx < split_x) {
        Ah = Ah0; Al = Al0; Wf = Wf0; bias = bias0;
        n0 = bx * 64; Ntot = Ntot0; relu = relu0; mode = mode0; Cm = C0;
    } else {
        Ah = Ah2; Al = Al2; Wf = Wf2; bias = bias2;
        n0 = (bx - split_x) * 64; Ntot = Ntot2; relu = 0; mode = mode2; Cm = C2;
    }

    unsigned aA_rel = (unsigned)((wm*32 + (lane & 15))*80 + (lane >> 4)*16);
    unsigned aB_rel = (unsigned)((wn*16 + ((lane >> 4) & 1)*8 + (lane & 7))*80 + (((lane >> 3) & 1))*16);

    float acc[2][2][4] = {};

    fill_bb(Ah, Al, Wf, sbase, 0, m0, n0, 0, M, K, tid);
    fill_bb(Ah, Al, Wf, sbase, 1, m0, n0, 1, M, K, tid);

    for (int t = 0; t < NT; t++) {
        if (t + 1 < NT) cp_wait1(); else cp_wait0();
        __syncthreads();
        if (t + 2 < NT) {
            fill_bb(Ah, Al, Wf, sbase, (t + 2) % 3, m0, n0, t + 2, M, K, tid);
        }
        unsigned sA = sbase + (unsigned)((t % 3)*STG_SZ);
        unsigned sB = sA + 10240u;
        #pragma unroll
        for (int kk = 0; kk < 2; kk++) {
            unsigned ah[2][4], al[2][4], bw[4];
            #pragma unroll
            for (int im = 0; im < 2; im++) {
                ldsm4(ah[im], sA + aA_rel + im*1280 + kk*32);
                ldsm4(al[im], sA + 5120u + aA_rel + im*1280 + kk*32);
            }
            ldsm4(bw, sB + aB_rel + kk*32);
            #pragma unroll
            for (int im = 0; im < 2; im++) {
                mma_f16(acc[im][0], ah[im], bw[0], bw[1]);
                mma_f16(acc[im][1], ah[im], bw[2], bw[3]);
            }
            #pragma unroll
            for (int im = 0; im < 2; im++) {
                mma_f16(acc[im][0], al[im], bw[0], bw[1]);
                mma_f16(acc[im][1], al[im], bw[2], bw[3]);
            }
        }
    }

    // ---- epilogue ----
    #pragma unroll
    for (int im = 0; im < 2; im++) {
        int r0 = m0 + wm*32 + im*16 + g;
        #pragma unroll
        for (int in_ = 0; in_ < 2; in_++) {
            int gcol = n0 + wn*16 + in_*8 + qd*2;
            float bv0 = bias[gcol], bv1 = bias[gcol+1];
            float v0 = acc[im][in_][0] + bv0;
            float v1 = acc[im][in_][1] + bv1;
            float v2 = acc[im][in_][2] + bv0;
            float v3 = acc[im][in_][3] + bv1;
            if (relu) {
                v0 = fmaxf(v0, 0.f); v1 = fmaxf(v1, 0.f);
                v2 = fmaxf(v2, 0.f); v3 = fmaxf(v3, 0.f);
            }
            if (mode == 2) {
                __half h0,l0,h1,l1;
                if (r0 < M) {
                    split2h(v0, h0, l0); split2h(v1, h1, l1);
                    __half2 hh; hh.x = h0; hh.y = h1;
                    __half2 ll; ll.x = l0; ll.y = l1;
                    *(__half2*)(Oh + (size_t)r0*Ntot + gcol) = hh;
                    *(__half2*)(Ol + (size_t)r0*Ntot + gcol) = ll;
                }
                if (r0 + 8 < M) {
                    split2h(v2, h0, l0); split2h(v3, h1, l1);
                    __half2 hh; hh.x = h0; hh.y = h1;
                    __half2 ll; ll.x = l0; ll.y = l1;
                    *(__half2*)(Oh + (size_t)(r0+8)*Ntot + gcol) = hh;
                    *(__half2*)(Ol + (size_t)(r0+8)*Ntot + gcol) = ll;
                }
            } else if (mode == 1) {
                __half* Ch = (__half*)Cm;
                if (r0 < M)     *(__half2*)(Ch + (size_t)r0*Ntot + gcol)     = __floats2half2_rn(v0, v1);
                if (r0 + 8 < M) *(__half2*)(Ch + (size_t)(r0+8)*Ntot + gcol) = __floats2half2_rn(v2, v3);
            } else {
                float* Cc; int ldc, base;
                if (gcol < n_split) { Cc = Cm; ldc = n_split;        base = 0; }
                else                { Cc = C1; ldc = Ntot - n_split; base = n_split; }
                int cn = gcol - base;
                if (r0 < M)     *(float2*)(Cc + (size_t)r0*ldc + cn)     = make_float2(v0, v1);
                if (r0 + 8 < M) *(float2*)(Cc + (size_t)(r0+8)*ldc + cn) = make_float2(v2, v3);
            }
        }
    }
}

// ---------------- ms-deform attention core (fused softmax; fp16 values) ----------------
__global__ void __launch_bounds__(256)
msdeform_kernel(const __half* __restrict__ val, const float* __restrict__ off,
                const float* __restrict__ aw, const float* __restrict__ ref,
                __half* __restrict__ oh, __half* __restrict__ ol)
{
    int warp = blockIdx.x * (blockDim.x >> 5) + (threadIdx.x >> 5);
    int lane = threadIdx.x & 31;
    if (warp >= NB*LQT*NHH) return;
    int h  = warp & 7;
    int bq = warp >> 3;
    int q  = bq % LQT;
    int b  = bq / LQT;
    float gx = ref[q*2], gy = ref[q*2+1];
    const float* offp = off + (size_t)bq*DD  + h*32;
    const float* awp  = aw  + (size_t)bq*128 + h*16;
    float w16[16];
    float mx = -1e30f;
    #pragma unroll
    for (int i = 0; i < 16; i++) { w16[i] = awp[i]; mx = fmaxf(mx, w16[i]); }
    float ssum = 0.f;
    #pragma unroll
    for (int i = 0; i < 16; i++) { w16[i] = __expf(w16[i] - mx); ssum += w16[i]; }
    float inv = 1.f / ssum;
    float acc = 0.f;
    #pragma unroll
    for (int l = 0; l < 4; l++) {
        int Wl = c_W[l], Hl = c_H[l], st = c_start[l];
        float fW = (float)Wl, fH = (float)Hl;
        const __half* vb = val + ((size_t)b*LQT + st)*DD + h*32 + lane;
        #pragma unroll
        for (int p = 0; p < 4; p++) {
            float ox = offp[(l*4+p)*2+0], oy = offp[(l*4+p)*2+1];
            float a  = w16[l*4+p] * inv;
            float x = (gx + ox / fW) * fW - 0.5f;
            float y = (gy + oy / fH) * fH - 0.5f;
            float x0f = floorf(x), y0f = floorf(y);
            float tx = x - x0f, ty = y - y0f;
            int x0 = (int)x0f, y0 = (int)y0f;
            float w00 = (1.f-tx)*(1.f-ty)*a;
            float w10 = tx*(1.f-ty)*a;
            float w01 = (1.f-tx)*ty*a;
            float w11 = tx*ty*a;
            bool xv0 = (x0   >= 0) && (x0   < Wl);
            bool xv1 = (x0+1 >= 0) && (x0+1 < Wl);
            bool yv0 = (y0   >= 0) && (y0   < Hl);
            bool yv1 = (y0+1 >= 0) && (y0+1 < Hl);
            if (xv0 && yv0) acc += w00 * __half2float(vb[(size_t)(y0*Wl + x0)     * DD]);
            if (xv1 && yv0) acc += w10 * __half2float(vb[(size_t)(y0*Wl + x0 + 1) * DD]);
            if (xv0 && yv1) acc += w01 * __half2float(vb[(size_t)((y0+1)*Wl + x0)     * DD]);
            if (xv1 && yv1) acc += w11 * __half2float(vb[(size_t)((y0+1)*Wl + x0 + 1) * DD]);
        }
    }
    __half hh, ll;
    split2h(acc, hh, ll);
    size_t o = (size_t)bq*DD + h*32 + lane;
    oh[o] = hh; ol[o] = ll;
}

// ---------------- residual + LayerNorm: warp-per-row ----------------
__global__ void __launch_bounds__(256)
addln_kernel(float* __restrict__ src, const float* __restrict__ res,
             const float* __restrict__ g, const float* __restrict__ b,
             __half* __restrict__ oh, __half* __restrict__ ol,
             __half* __restrict__ qh, __half* __restrict__ ql,
             const float* __restrict__ pos)
{
    int warp = threadIdx.x >> 5, lane = threadIdx.x & 31;
    int row = blockIdx.x*8 + warp;
    size_t base = (size_t)row*DD;
    const float4* s4 = (const float4*)(src + base);
    const float4* r4 = (const float4*)(res + base);
    float4 sa = s4[lane], sb = s4[lane+32];
    float4 ra = r4[lane], rb = r4[lane+32];
    float x[8];
    x[0]=sa.x+ra.x; x[1]=sa.y+ra.y; x[2]=sa.z+ra.z; x[3]=sa.w+ra.w;
    x[4]=sb.x+rb.x; x[5]=sb.y+rb.y; x[6]=sb.z+rb.z; x[7]=sb.w+rb.w;
    float sum = 0.f;
    #pragma unroll
    for (int i = 0; i < 8; i++) sum += x[i];
    #pragma unroll
    for (int o = 16; o > 0; o >>= 1) sum += __shfl_xor_sync(0xffffffffu, sum, o);
    float mean = sum * (1.f/DD);
    float var = 0.f;
    #pragma unroll
    for (int i = 0; i < 8; i++) { float d = x[i]-mean; var += d*d; }
    #pragma unroll
    for (int o = 16; o > 0; o >>= 1) var += __shfl_xor_sync(0xffffffffu, var, o);
    float rstd = rsqrtf(var * (1.f/DD) + 1e-5f);
    int c0 = lane*4, c1 = 128 + lane*4;
    float4 g0 = *(const float4*)(g + c0), g1 = *(const float4*)(g + c1);
    float4 b0 = *(const float4*)(b + c0), b1 = *(const float4*)(b + c1);
    float y[8];
    y[0]=(x[0]-mean)*rstd*g0.x+b0.x; y[1]=(x[1]-mean)*rstd*g0.y+b0.y;
    y[2]=(x[2]-mean)*rstd*g0.z+b0.z; y[3]=(x[3]-mean)*rstd*g0.w+b0.w;
    y[4]=(x[4]-mean)*rstd*g1.x+b1.x; y[5]=(x[5]-mean)*rstd*g1.y+b1.y;
    y[6]=(x[6]-mean)*rstd*g1.z+b1.z; y[7]=(x[7]-mean)*rstd*g1.w+b1.w;
    float4* w4 = (float4*)(src + base);
    w4[lane]    = make_float4(y[0],y[1],y[2],y[3]);
    w4[lane+32] = make_float4(y[4],y[5],y[6],y[7]);
    #pragma unroll
    for (int hblk = 0; hblk < 2; hblk++) {
        size_t o = base + (hblk ? (size_t)c1 : (size_t)c0);
        #pragma unroll
        for (int p = 0; p < 2; p++) {
            __half h0,l0,h1,l1;
            split2h(y[hblk*4+2*p],   h0, l0);
            split2h(y[hblk*4+2*p+1], h1, l1);
            __half2 hh; hh.x=h0; hh.y=h1;
            __half2 ll; ll.x=l0; ll.y=l1;
            *(__half2*)(oh + o + 2*p) = hh;
            *(__half2*)(ol + o + 2*p) = ll;
        }
    }
    if (qh) {
        const float4* p4 = (const float4*)(pos + base);
        float4 pa = p4[lane], pb = p4[lane+32];
        float z[8];
        z[0]=y[0]+pa.x; z[1]=y[1]+pa.y; z[2]=y[2]+pa.z; z[3]=y[3]+pa.w;
        z[4]=y[4]+pb.x; z[5]=y[5]+pb.y; z[6]=y[6]+pb.z; z[7]=y[7]+pb.w;
        #pragma unroll
        for (int hblk = 0; hblk < 2; hblk++) {
            size_t o = base + (hblk ? (size_t)c1 : (size_t)c0);
            #pragma unroll
            for (int p = 0; p < 2; p++) {
                __half h0,l0,h1,l1;
                split2h(z[hblk*4+2*p],   h0, l0);
                split2h(z[hblk*4+2*p+1], h1, l1);
                __half2 hh; hh.x=h0; hh.y=h1;
                __half2 ll; ll.x=l0; ll.y=l1;
                *(__half2*)(qh + o + 2*p) = hh;
                *(__half2*)(ql + o + 2*p) = ll;
            }
        }
    }
}

// ---------------- finalize ----------------
__global__ void finalize_kernel(const float* __restrict__ src, float* __restrict__ out, int out_size)
{
    int i = blockIdx.x*blockDim.x + threadIdx.x;
    if (i >= out_size) return;
    const int n = NB*LQT*DD;
    if (i < n) { out[i] = src[i]; return; }
    int j = i - n;
    float v;
    if (j < 4)       v = (float)c_start[j];
    else if (j < 12) v = (float)c_H[(j-4) >> 1];
    else             v = 1.0f;
    out[i] = v;
}

// ---------------- host orchestration ----------------
extern "C" void kernel_launch(void* const* d_in, const int* in_sizes, int n_in,
                              void* d_out, int out_size)
{
    (void)n_in;
    const float *X[4], *FW[4], *FB[4];
    if (in_sizes[1] == 65536) {
        for (int i = 0; i < 4; i++) {
            X[i]  = (const float*)d_in[3*i+0];
            FW[i] = (const float*)d_in[3*i+1];
            FB[i] = (const float*)d_in[3*i+2];
        }
    } else {
        for (int i = 0; i < 4; i++) {
            X[i]  = (const float*)d_in[i];
            FW[i] = (const float*)d_in[4+2*i];
            FB[i] = (const float*)d_in[5+2*i];
        }
    }
    const float* gn_g  = (const float*)d_in[12];
    const float* gn_b  = (const float*)d_in[13];
    const float* lemb  = (const float*)d_in[14];
    const float* off_w = (const float*)d_in[15];
    const float* off_b = (const float*)d_in[16];
    const float* aw_w  = (const float*)d_in[17];
    const float* aw_b  = (const float*)d_in[18];
    const float* val_w = (const float*)d_in[19];
    const float* val_b = (const float*)d_in[20];
    const float* out_w = (const float*)d_in[21];
    const float* out_b = (const float*)d_in[22];
    const float* ln1_g = (const float*)d_in[23];
    const float* ln1_b = (const float*)d_in[24];
    const float* l1_w  = (const float*)d_in[25];
    const float* l1_b  = (const float*)d_in[26];
    const float* l2_w  = (const float*)d_in[27];
    const float* l2_b  = (const float*)d_in[28];
    const float* ln2_g = (const float*)d_in[29];
    const float* ln2_b = (const float*)d_in[30];

    float *src, *pos, *off, *aw, *val, *att, *ref, *cbias;
    __half *wf, *qh, *ql, *sh, *sl, *th, *tl, *msh, *msl, *hbh, *hbl;
    cudaGetSymbolAddress((void**)&src,   g_src);
    cudaGetSymbolAddress((void**)&pos,   g_pos);
    cudaGetSymbolAddress((void**)&off,   g_off);
    cudaGetSymbolAddress((void**)&aw,    g_aw);
    cudaGetSymbolAddress((void**)&val,   g_val);
    cudaGetSymbolAddress((void**)&att,   g_att);
    cudaGetSymbolAddress((void**)&ref,   g_ref);
    cudaGetSymbolAddress((void**)&cbias, g_cbias);
    cudaGetSymbolAddress((void**)&wf,    g_wf);
    cudaGetSymbolAddress((void**)&qh,    g_qh);
    cudaGetSymbolAddress((void**)&ql,    g_ql);
    cudaGetSymbolAddress((void**)&sh,    g_sh);
    cudaGetSymbolAddress((void**)&sl,    g_sl);
    cudaGetSymbolAddress((void**)&th,    g_th);
    cudaGetSymbolAddress((void**)&tl,    g_tl);
    cudaGetSymbolAddress((void**)&msh,   g_msh);
    cudaGetSymbolAddress((void**)&msl,   g_msl);
    cudaGetSymbolAddress((void**)&hbh,   g_hbh);
    cudaGetSymbolAddress((void**)&hbl,   g_hbl);

    cudaFuncSetAttribute(gemm_bb_kernel,
        cudaFuncAttributeMaxDynamicSharedMemorySize, SMEM_BB);

    setup_kernel<<<(N_WB + LQT*DD + 255)/256, 256>>>(
        off_w, aw_w, val_w, out_w, l1_w, l2_w, off_b, aw_b, wf, cbias, lemb, pos, ref);
    tokenizer_kernel<<<1536, 256>>>(X[0], X[1], X[2], X[3],
                                    FW[0], FW[1], FW[2], FW[3],
                                    FB[0], FB[1], FB[2], FB[3], src);
    gn_kernel<<<4*2*32, 256>>>(src, gn_g, gn_b, pos, sh, sl, qh, ql);

    const int GY = (MTOT + 63)/64;  // 383
    dim3 g_oawval(10, GY), g_256(4, GY), g_l1(16, GY);
    const int BIGX = 1 << 20;

    for (int l = 0; l < NLAY; l++) {
        // merged: oaw GEMM (bx 0..5, from q-split) + val GEMM (bx 6..9, from s-split)
        gemm_bb_kernel<<<g_oawval, 256, SMEM_BB>>>(
            qh, ql, wf + OFF_OAW + (size_t)l*98304, cbias + l*384,
            off, aw, 256, (__half*)0, (__half*)0,
            MTOT, 384, 256, 0, 0,
            6,
            sh, sl, wf + OFF_VAL + (size_t)l*65536, val_b + l*DD,
            val, 256, 1);
        msdeform_kernel<<<MTOT, 256>>>((const __half*)val, off, aw, ref, msh, msl);
        gemm_bb_kernel<<<g_256, 256, SMEM_BB>>>(
            msh, msl, wf + OFF_OUT + (size_t)l*65536, out_b + l*DD,
            att, (float*)0, 256, (__half*)0, (__half*)0,
            MTOT, 256, 256, 0, 0,
            BIGX, (__half*)0, (__half*)0, (__half*)0, (const float*)0, (float*)0, 0, 0);
        addln_kernel<<<MTOT/8, 256>>>(src, att, ln1_g + l*DD, ln1_b + l*DD,
            th, tl, (__half*)0, (__half*)0, (const float*)0);
        gemm_bb_kernel<<<g_l1, 256, SMEM_BB>>>(
            th, tl, wf + OFF_L1 + (size_t)l*262144, l1_b + l*DFF_,
            (float*)0, (float*)0, 1024, hbh, hbl,
            MTOT, 1024, 256, 1, 2,
            BIGX, (__half*)0, (__half*)0, (__half*)0, (const float*)0, (float*)0, 0, 0);
        gemm_bb_kernel<<<g_256, 256, SMEM_BB>>>(
            hbh, hbl, wf + OFF_L2 + (size_t)l*262144, l2_b + l*DD,
            att, (float*)0, 256, (__half*)0, (__half*)0,
            MTOT, 256, 1024, 0, 0,
            BIGX, (__half*)0, (__half*)0, (__half*)0, (const float*)0, (float*)0, 0, 0);
        addln_kernel<<<MTOT/8, 256>>>(src, att, ln2_g + l*DD, ln2_b + l*DD,
            sh, sl, qh, ql, pos);
    }

    finalize_kernel<<<(out_size + 255)/256, 256>>>(src, (float*)d_out, out_size);
}

// round 17
// speedup vs baseline: 1.3638x; 1.3638x over previous
#include <cuda_runtime.h>
#include <cuda_bf16.h>
#include <cuda_fp16.h>
#include <stdint.h>
#include <math.h>

// ---------------- problem constants ----------------
#define NB    2
#define DD    256
#define LQT   12240
#define NHH   8
#define NLAY  6
#define DFF_  1024
#define MTOT  (NB*LQT)   // 24480

__constant__ int c_H[4]     = {96,48,24,12};
__constant__ int c_W[4]     = {96,48,24,12};
__constant__ int c_start[4] = {0,9216,11520,12096};
__constant__ int c_len[4]   = {9216,2304,576,144};
__constant__ int c_cin[4]   = {256,512,768,1024};

// ---------------- scratch (device globals; no allocation) ----------------
__device__ float g_src[NB*LQT*DD];
__device__ float g_pos[NB*LQT*DD];
__device__ float g_off[NB*LQT*DD];
__device__ float g_aw [NB*LQT*128];
__device__ float g_val[NB*LQT*DD];    // fp16 payload
__device__ float g_att[NB*LQT*DD];
__device__ float g_ref[LQT*2];
__device__ float g_cbias[NLAY*384];
// fp16 hi/lo activation buffers (GEMM A-side inputs)
__device__ __half g_qh [MTOT*DD],  g_ql [MTOT*DD];
__device__ __half g_sh [MTOT*DD],  g_sl [MTOT*DD];
__device__ __half g_th [MTOT*DD],  g_tl [MTOT*DD];
__device__ __half g_msh[MTOT*DD],  g_msl[MTOT*DD];
__device__ __half g_hbh[MTOT*DFF_], g_hbl[MTOT*DFF_];

// fp16 weights; oaw fused per layer: off(65536)+aw(32768)
#define OFF_OAW 0
#define OFF_VAL 589824
#define OFF_OUT 983040
#define OFF_L1  1376256
#define OFF_L2  2949120
#define W_TOTAL 4521984
__device__ __half g_wf[W_TOTAL];

__device__ __forceinline__ int lvl_of(int q) {
    return (q < 9216) ? 0 : (q < 11520) ? 1 : (q < 12096) ? 2 : 3;
}

__device__ __forceinline__ float blockSum(float v) {
    __shared__ float sh[8];
    int lane = threadIdx.x & 31, w = threadIdx.x >> 5;
    #pragma unroll
    for (int o = 16; o > 0; o >>= 1) v += __shfl_xor_sync(0xffffffffu, v, o);
    if (lane == 0) sh[w] = v;
    __syncthreads();
    if (w == 0) {
        float r = (lane < 8) ? sh[lane] : 0.f;
        #pragma unroll
        for (int o = 4; o > 0; o >>= 1) r += __shfl_xor_sync(0xffffffffu, r, o);
        if (lane == 0) sh[0] = r;
    }
    __syncthreads();
    float res = sh[0];
    __syncthreads();
    return res;
}

__device__ __forceinline__ void split2h(float x, __half& h, __half& l) {
    h = __float2half_rn(x);
    l = __float2half_rn(x - __half2float(h));
}

// ---------------- launch 0: weight convert + concat bias + pos/ref ----------------
#define N_WB (W_TOTAL + NLAY*384)
__global__ void setup_kernel(
    const float* __restrict__ off_w, const float* __restrict__ aw_w,
    const float* __restrict__ val_w, const float* __restrict__ out_w,
    const float* __restrict__ l1_w,  const float* __restrict__ l2_w,
    const float* __restrict__ off_b, const float* __restrict__ aw_b,
    __half* __restrict__ wf, float* __restrict__ cbias,
    const float* __restrict__ lemb, float* __restrict__ pos, float* __restrict__ ref)
{
    int i = blockIdx.x*blockDim.x + threadIdx.x;
    if (i < W_TOTAL) {
        float x; long long o;
        if (i < 393216) {
            int l = i >> 16, r = i & 65535;
            x = off_w[i]; o = (long long)l*98304 + r;
        } else if (i < 589824) {
            int j = i - 393216;
            int l = j >> 15, r = j & 32767;
            x = aw_w[j]; o = (long long)l*98304 + 65536 + r;
        } else if (i < 983040) {
            x = val_w[i - 589824]; o = i;
        } else if (i < 1376256) {
            x = out_w[i - 983040]; o = i;
        } else if (i < 2949120) {
            x = l1_w[i - 1376256]; o = i;
        } else {
            x = l2_w[i - 2949120]; o = i;
        }
        wf[o] = __float2half_rn(x);
        return;
    }
    if (i < N_WB) {
        int j = i - W_TOTAL;
        int l = j / 384, c = j % 384;
        cbias[j] = (c < 256) ? off_b[l*256 + c] : aw_b[l*128 + (c - 256)];
        return;
    }
    int idx = i - N_WB;
    if (idx >= LQT*DD) return;
    int qq = idx >> 8, d = idx & 255;
    int lvl = lvl_of(qq);
    int st = c_start[lvl], H = c_H[lvl], W = c_W[lvl];
    int p = qq - st; int y = p / W, x = p % W;
    const float TWO_PI = 6.28318530717958647692f;
    const float LN1E4_64 = 0.14391156831212787f;
    float v;
    if (d < 128) {
        float e = (float)(y+1) / ((float)H + 1e-6f) * TWO_PI;
        int k = d >> 1;
        float u = e * expf(-LN1E4_64 * (float)k);
        v = (d & 1) ? cosf(u) : sinf(u);
    } else {
        int dd = d - 128;
        float e = (float)(x+1) / ((float)W + 1e-6f) * TWO_PI;
        int k = dd >> 1;
        float u = e * expf(-LN1E4_64 * (float)k);
        v = (dd & 1) ? cosf(u) : sinf(u);
    }
    v += lemb[lvl*DD + d];
    pos[(size_t)qq*DD + d] = v;
    pos[(size_t)(LQT + qq)*DD + d] = v;
    if (d == 0) {
        ref[qq*2+0] = ((float)x + 0.5f) / (float)W;
        ref[qq*2+1] = ((float)y + 0.5f) / (float)H;
    }
}

// ---------------- launch 1: tokenizer (all levels/batches) ----------------
__global__ void __launch_bounds__(256)
tokenizer_kernel(const float* __restrict__ X0, const float* __restrict__ X1,
                 const float* __restrict__ X2, const float* __restrict__ X3,
                 const float* __restrict__ W0, const float* __restrict__ W1,
                 const float* __restrict__ W2, const float* __restrict__ W3,
                 const float* __restrict__ B0, const float* __restrict__ B1,
                 const float* __restrict__ B2, const float* __restrict__ B3,
                 float* __restrict__ src)
{
    int bid = blockIdx.x;
    int lvl, base;
    if      (bid < 1152) { lvl = 0; base = 0; }
    else if (bid < 1440) { lvl = 1; base = 1152; }
    else if (bid < 1512) { lvl = 2; base = 1440; }
    else                 { lvl = 3; base = 1512; }
    int HW = c_len[lvl], K = c_cin[lvl];
    int rem = bid - base;
    int span = ((HW + 63)/64) * 4;
    int b = rem / span; rem -= b*span;
    int m0 = (rem >> 2) * 64, n0 = (rem & 3) * 64;
    const float* A = (lvl==0?X0:lvl==1?X1:lvl==2?X2:X3) + (size_t)b*K*HW;
    const float* W = (lvl==0?W0:lvl==1?W1:lvl==2?W2:W3);
    const float* bias = (lvl==0?B0:lvl==1?B1:lvl==2?B2:B3);
    float* C = src + ((size_t)b*LQT + c_start[lvl]) * DD;
    int M = HW, N = DD;

    __shared__ __align__(16) float As[16][68];
    __shared__ __align__(16) float Ws[16][68];
    int tid = threadIdx.x;
    int tx = tid & 15, ty = tid >> 4;
    int ak = tid >> 4, amq = (tid & 15) * 4;
    int wn = tid >> 2, wk  = (tid & 3) * 4;
    bool aok = (m0 + amq) < M;
    float acc[4][4] = {};
    for (int k0 = 0; k0 < K; k0 += 16) {
        float4 a4 = aok ? *(const float4*)(A + (size_t)(k0+ak)*M + m0 + amq)
                        : make_float4(0.f,0.f,0.f,0.f);
        *(float4*)&As[ak][amq] = a4;
        float4 w4 = *(const float4*)(W + (size_t)(n0+wn)*K + k0 + wk);
        Ws[wk+0][wn]=w4.x; Ws[wk+1][wn]=w4.y; Ws[wk+2][wn]=w4.z; Ws[wk+3][wn]=w4.w;
        __syncthreads();
        #pragma unroll
        for (int k = 0; k < 16; k++) {
            float4 a = *(const float4*)&As[k][ty*4];
            float4 w = *(const float4*)&Ws[k][tx*4];
            float ar[4] = {a.x,a.y,a.z,a.w}, wr[4] = {w.x,w.y,w.z,w.w};
            #pragma unroll
            for (int i = 0; i < 4; i++)
                #pragma unroll
                for (int j = 0; j < 4; j++)
                    acc[i][j] = fmaf(ar[i], wr[j], acc[i][j]);
        }
        __syncthreads();
    }
    #pragma unroll
    for (int i = 0; i < 4; i++) {
        int m = m0 + ty*4 + i;
        if (m >= M) break;
        #pragma unroll
        for (int j = 0; j < 4; j++) {
            int n = n0 + tx*4 + j;
            C[(size_t)m*N + n] = acc[i][j] + bias[n];
        }
    }
}

// ---------------- launch 2: GroupNorm + prep splits (fused) ----------------
__global__ void __launch_bounds__(256)
gn_kernel(float* __restrict__ src, const float* __restrict__ g, const float* __restrict__ b,
          const float* __restrict__ pos,
          __half* __restrict__ sh_, __half* __restrict__ sl_,
          __half* __restrict__ qh_, __half* __restrict__ ql_)
{
    int grp = blockIdx.x & 31;
    int bb  = (blockIdx.x >> 5) & 1;
    int lvl = blockIdx.x >> 6;
    int L = c_len[lvl], st = c_start[lvl];
    size_t gbase = ((size_t)bb*LQT + st) * DD;
    float* base = src + gbase;
    int n = L * 8;
    float s = 0.f;
    for (int i = threadIdx.x; i < n; i += 256)
        s += base[(size_t)(i>>3)*DD + grp*8 + (i&7)];
    float mean = blockSum(s) / (float)n;
    float s2 = 0.f;
    for (int i = threadIdx.x; i < n; i += 256) {
        float d = base[(size_t)(i>>3)*DD + grp*8 + (i&7)] - mean;
        s2 += d*d;
    }
    float rstd = rsqrtf(blockSum(s2) / (float)n + 1e-5f);
    for (int i = threadIdx.x; i < n; i += 256) {
        int c = grp*8 + (i&7);
        size_t id = (size_t)(i>>3)*DD + c;
        float y = (base[id] - mean) * rstd * g[lvl*DD + c] + b[lvl*DD + c];
        base[id] = y;
        size_t gid = gbase + id;
        __half h, l;
        split2h(y, h, l);          sh_[gid] = h; sl_[gid] = l;
        split2h(y + pos[gid], h, l); qh_[gid] = h; ql_[gid] = l;
    }
}

// ---------------- fp16x2 cp.async tensor-core GEMM (R15 geometry) ----------------
// BM=64, BN=128, 256 thr (8 warps 2m x 4n, warp tile 32x32), BK=32, 3-stage.
// Stage layout: Ah(5120) Al(5120) B(10240) = 20480 B. 3 CTAs/SM.
#define STG_SZ 20480
#define SMEM_BB (3*STG_SZ)

__device__ __forceinline__ void mma_f16(float c[4], const unsigned a[4],
                                        unsigned b0, unsigned b1)
{
    asm volatile("mma.sync.aligned.m16n8k16.row.col.f32.f16.f16.f32 "
        "{%0,%1,%2,%3}, {%4,%5,%6,%7}, {%8,%9}, {%0,%1,%2,%3};"
        : "+f"(c[0]), "+f"(c[1]), "+f"(c[2]), "+f"(c[3])
        : "r"(a[0]), "r"(a[1]), "r"(a[2]), "r"(a[3]), "r"(b0), "r"(b1));
}
__device__ __forceinline__ void ldsm4(unsigned r[4], unsigned a) {
    asm volatile("ldmatrix.sync.aligned.m8n8.x4.shared.b16 {%0,%1,%2,%3}, [%4];"
        : "=r"(r[0]), "=r"(r[1]), "=r"(r[2]), "=r"(r[3]) : "r"(a));
}
__device__ __forceinline__ void cp16(unsigned dst, const void* src) {
    asm volatile("cp.async.cg.shared.global [%0], [%1], 16;" :: "r"(dst), "l"(src));
}
__device__ __forceinline__ void cp16z(unsigned dst, const void* src, int sz) {
    asm volatile("cp.async.cg.shared.global [%0], [%1], 16, %2;" :: "r"(dst), "l"(src), "r"(sz));
}
__device__ __forceinline__ void cp_commit() { asm volatile("cp.async.commit_group;"); }
__device__ __forceinline__ void cp_wait1()  { asm volatile("cp.async.wait_group 1;"); }
__device__ __forceinline__ void cp_wait0()  { asm volatile("cp.async.wait_group 0;"); }

__device__ __forceinline__ void fill_bb(
    const __half* __restrict__ Ah, const __half* __restrict__ Al,
    const __half* __restrict__ Wf,
    unsigned sbase, int stage, int m0, int n0, int t, int M, int K, int tid)
{
    int row = tid >> 2, seg = tid & 3;          // 64 rows x 4 16B-segments
    unsigned so = sbase + (unsigned)(stage*STG_SZ);
    unsigned ao = so + (unsigned)(row*80 + seg*16);
    size_t ga = (size_t)(m0 + row)*K + t*32 + seg*8;
    int asz = ((m0 + row) < M) ? 16 : 0;
    cp16z(ao,        Ah + ga, asz);
    cp16z(ao + 5120, Al + ga, asz);
    unsigned bo = so + 10240u + (unsigned)(row*80 + seg*16);
    size_t gb = (size_t)(n0 + row)*K + t*32 + seg*8;
    cp16(bo,        Wf + gb);
    cp16(bo + 5120, Wf + gb + (size_t)64*K);   // rows 64..127
    cp_commit();
}

__global__ void __launch_bounds__(256, 3)
gemm_bb_kernel(const __half* __restrict__ Ah0, const __half* __restrict__ Al0,
               const __half* __restrict__ Wf0, const float* __restrict__ bias0,
               float* __restrict__ C0, float* __restrict__ C1, int n_split,
               __half* __restrict__ Oh, __half* __restrict__ Ol,
               int M, int Ntot0, int K, int relu0, int mode0,
               int split_x,
               const __half* __restrict__ Ah2, const __half* __restrict__ Al2,
               const __half* __restrict__ Wf2, const float* __restrict__ bias2,
               float* __restrict__ C2, int Ntot2, int mode2)
{
    extern __shared__ __align__(16) char smem[];
    unsigned sbase = (unsigned)__cvta_generic_to_shared(smem);
    int tid  = threadIdx.x;
    int lane = tid & 31, warp = tid >> 5;
    int wm = warp & 1, wn = warp >> 1;          // 2(m) x 4(n), warp tile 32x32
    int bx = blockIdx.x;
    int m0 = blockIdx.y * 64;
    int g = lane >> 2, qd = lane & 3;
    const int NT = K / 32;

    const __half *Ah, *Al, *Wf; const float* bias;
    int n0, Ntot, relu, mode;
    float* Cm;
    if (bx < split_x) {
        Ah = Ah0; Al = Al0; Wf = Wf0; bias = bias0;
        n0 = bx * 128; Ntot = Ntot0; relu = relu0; mode = mode0; Cm = C0;
    } else {
        Ah = Ah2; Al = Al2; Wf = Wf2; bias = bias2;
        n0 = (bx - split_x) * 128; Ntot = Ntot2; relu = 0; mode = mode2; Cm = C2;
    }

    unsigned aA_rel = (unsigned)((wm*32 + (lane & 15))*80 + (lane >> 4)*16);
    unsigned aB_rel = (unsigned)((wn*32 + ((lane >> 4) & 1)*8 + (lane & 7))*80 + ((lane >> 3) & 1)*16);

    float acc[2][4][4] = {};

    fill_bb(Ah, Al, Wf, sbase, 0, m0, n0, 0, M, K, tid);
    fill_bb(Ah, Al, Wf, sbase, 1, m0, n0, 1, M, K, tid);

    for (int t = 0; t < NT; t++) {
        if (t + 1 < NT) cp_wait1(); else cp_wait0();
        __syncthreads();
        if (t + 2 < NT) {
            fill_bb(Ah, Al, Wf, sbase, (t + 2) % 3, m0, n0, t + 2, M, K, tid);
        }
        unsigned sA = sbase + (unsigned)((t % 3)*STG_SZ);
        unsigned sB = sA + 10240u;
        #pragma unroll
        for (int kk = 0; kk < 2; kk++) {
            unsigned ah[2][4], al[2][4], bw[2][4];
            #pragma unroll
            for (int im = 0; im < 2; im++) {
                ldsm4(ah[im], sA + aA_rel + im*1280 + kk*32);
                ldsm4(al[im], sA + 5120u + aA_rel + im*1280 + kk*32);
            }
            #pragma unroll
            for (int jn = 0; jn < 2; jn++)
                ldsm4(bw[jn], sB + aB_rel + jn*1280 + kk*32);
            #pragma unroll
            for (int jn = 0; jn < 2; jn++)
                #pragma unroll
                for (int im = 0; im < 2; im++) {
                    mma_f16(acc[im][2*jn],   ah[im], bw[jn][0], bw[jn][1]);
                    mma_f16(acc[im][2*jn+1], ah[im], bw[jn][2], bw[jn][3]);
                }
            #pragma unroll
            for (int jn = 0; jn < 2; jn++)
                #pragma unroll
                for (int im = 0; im < 2; im++) {
                    mma_f16(acc[im][2*jn],   al[im], bw[jn][0], bw[jn][1]);
                    mma_f16(acc[im][2*jn+1], al[im], bw[jn][2], bw[jn][3]);
                }
        }
    }

    // ---- epilogue ----
    #pragma unroll
    for (int im = 0; im < 2; im++) {
        int r0 = m0 + wm*32 + im*16 + g;
        #pragma unroll
        for (int in_ = 0; in_ < 4; in_++) {
            int gcol = n0 + wn*32 + in_*8 + qd*2;
            float bv0 = bias[gcol], bv1 = bias[gcol+1];
            float v0 = acc[im][in_][0] + bv0;
            float v1 = acc[im][in_][1] + bv1;
            float v2 = acc[im][in_][2] + bv0;
            float v3 = acc[im][in_][3] + bv1;
            if (relu) {
                v0 = fmaxf(v0, 0.f); v1 = fmaxf(v1, 0.f);
                v2 = fmaxf(v2, 0.f); v3 = fmaxf(v3, 0.f);
            }
            if (mode == 2) {
                __half h0,l0,h1,l1;
                if (r0 < M) {
                    split2h(v0, h0, l0); split2h(v1, h1, l1);
                    __half2 hh; hh.x = h0; hh.y = h1;
                    __half2 ll; ll.x = l0; ll.y = l1;
                    *(__half2*)(Oh + (size_t)r0*Ntot + gcol) = hh;
                    *(__half2*)(Ol + (size_t)r0*Ntot + gcol) = ll;
                }
                if (r0 + 8 < M) {
                    split2h(v2, h0, l0); split2h(v3, h1, l1);
                    __half2 hh; hh.x = h0; hh.y = h1;
                    __half2 ll; ll.x = l0; ll.y = l1;
                    *(__half2*)(Oh + (size_t)(r0+8)*Ntot + gcol) = hh;
                    *(__half2*)(Ol + (size_t)(r0+8)*Ntot + gcol) = ll;
                }
            } else if (mode == 1) {
                __half* Ch = (__half*)Cm;
                if (r0 < M)     *(__half2*)(Ch + (size_t)r0*Ntot + gcol)     = __floats2half2_rn(v0, v1);
                if (r0 + 8 < M) *(__half2*)(Ch + (size_t)(r0+8)*Ntot + gcol) = __floats2half2_rn(v2, v3);
            } else {
                float* Cc; int ldc, base;
                if (gcol < n_split) { Cc = Cm; ldc = n_split;        base = 0; }
                else                { Cc = C1; ldc = Ntot - n_split; base = n_split; }
                int cn = gcol - base;
                if (r0 < M)     *(float2*)(Cc + (size_t)r0*ldc + cn)     = make_float2(v0, v1);
                if (r0 + 8 < M) *(float2*)(Cc + (size_t)(r0+8)*ldc + cn) = make_float2(v2, v3);
            }
        }
    }
}

// ---------------- ms-deform attention core v2: 2 heads per warp, half2 gathers ----------------
__global__ void __launch_bounds__(256)
msdeform_kernel(const __half* __restrict__ val, const float* __restrict__ off,
                const float* __restrict__ aw, const float* __restrict__ ref,
                __half* __restrict__ oh, __half* __restrict__ ol)
{
    int wid = blockIdx.x * (blockDim.x >> 5) + (threadIdx.x >> 5);
    int lane = threadIdx.x & 31;
    if (wid >= NB*LQT*4) return;
    int hp = wid & 3;                 // head pair 0..3
    int bq = wid >> 2;
    int q  = bq % LQT;
    int b  = bq / LQT;
    int h  = hp*2 + (lane >> 4);      // per-lane head
    int c  = hp*64 + lane*2;          // channel pair base
    float gx = ref[q*2], gy = ref[q*2+1];
    const float* offp = off + (size_t)bq*DD  + h*32;
    const float* awp  = aw  + (size_t)bq*128 + h*16;
    // in-register softmax over this head's 16 logits
    float w16[16];
    float mx = -1e30f;
    #pragma unroll
    for (int i = 0; i < 16; i++) { w16[i] = awp[i]; mx = fmaxf(mx, w16[i]); }
    float ssum = 0.f;
    #pragma unroll
    for (int i = 0; i < 16; i++) { w16[i] = __expf(w16[i] - mx); ssum += w16[i]; }
    float inv = 1.f / ssum;
    float acc0 = 0.f, acc1 = 0.f;
    #pragma unroll
    for (int l = 0; l < 4; l++) {
        int Wl = c_W[l], Hl = c_H[l], st = c_start[l];
        float fW = (float)Wl, fH = (float)Hl;
        const __half* vb = val + ((size_t)b*LQT + st)*DD + c;
        #pragma unroll
        for (int p = 0; p < 4; p++) {
            float ox = offp[(l*4+p)*2+0], oy = offp[(l*4+p)*2+1];
            float a  = w16[l*4+p] * inv;
            float x = (gx + ox / fW) * fW - 0.5f;
            float y = (gy + oy / fH) * fH - 0.5f;
            float x0f = floorf(x), y0f = floorf(y);
            float tx = x - x0f, ty = y - y0f;
            int x0 = (int)x0f, y0 = (int)y0f;
            float w00 = (1.f-tx)*(1.f-ty)*a;
            float w10 = tx*(1.f-ty)*a;
            float w01 = (1.f-tx)*ty*a;
            float w11 = tx*ty*a;
            bool xv0 = (x0   >= 0) && (x0   < Wl);
            bool xv1 = (x0+1 >= 0) && (x0+1 < Wl);
            bool yv0 = (y0   >= 0) && (y0   < Hl);
            bool yv1 = (y0+1 >= 0) && (y0+1 < Hl);
            if (xv0 && yv0) {
                float2 v2 = __half22float2(*(const __half2*)(vb + (size_t)(y0*Wl + x0)*DD));
                acc0 += w00 * v2.x; acc1 += w00 * v2.y;
            }
            if (xv1 && yv0) {
                float2 v2 = __half22float2(*(const __half2*)(vb + (size_t)(y0*Wl + x0 + 1)*DD));
                acc0 += w10 * v2.x; acc1 += w10 * v2.y;
            }
            if (xv0 && yv1) {
                float2 v2 = __half22float2(*(const __half2*)(vb + (size_t)((y0+1)*Wl + x0)*DD));
                acc0 += w01 * v2.x; acc1 += w01 * v2.y;
            }
            if (xv1 && yv1) {
                float2 v2 = __half22float2(*(const __half2*)(vb + (size_t)((y0+1)*Wl + x0 + 1)*DD));
                acc0 += w11 * v2.x; acc1 += w11 * v2.y;
            }
        }
    }
    __half h0, l0, h1, l1;
    split2h(acc0, h0, l0);
    split2h(acc1, h1, l1);
    __half2 hh; hh.x = h0; hh.y = h1;
    __half2 ll; ll.x = l0; ll.y = l1;
    size_t o = (size_t)bq*DD + c;
    *(__half2*)(oh + o) = hh;
    *(__half2*)(ol + o) = ll;
}

// ---------------- residual + LayerNorm: warp-per-row ----------------
__global__ void __launch_bounds__(256)
addln_kernel(float* __restrict__ src, const float* __restrict__ res,
             const float* __restrict__ g, const float* __restrict__ b,
             __half* __restrict__ oh, __half* __restrict__ ol,
             __half* __restrict__ qh, __half* __restrict__ ql,
             const float* __restrict__ pos)
{
    int warp = threadIdx.x >> 5, lane = threadIdx.x & 31;
    int row = blockIdx.x*8 + warp;
    size_t base = (size_t)row*DD;
    const float4* s4 = (const float4*)(src + base);
    const float4* r4 = (const float4*)(res + base);
    float4 sa = s4[lane], sb = s4[lane+32];
    float4 ra = r4[lane], rb = r4[lane+32];
    float x[8];
    x[0]=sa.x+ra.x; x[1]=sa.y+ra.y; x[2]=sa.z+ra.z; x[3]=sa.w+ra.w;
    x[4]=sb.x+rb.x; x[5]=sb.y+rb.y; x[6]=sb.z+rb.z; x[7]=sb.w+rb.w;
    float sum = 0.f;
    #pragma unroll
    for (int i = 0; i < 8; i++) sum += x[i];
    #pragma unroll
    for (int o = 16; o > 0; o >>= 1) sum += __shfl_xor_sync(0xffffffffu, sum, o);
    float mean = sum * (1.f/DD);
    float var = 0.f;
    #pragma unroll
    for (int i = 0; i < 8; i++) { float d = x[i]-mean; var += d*d; }
    #pragma unroll
    for (int o = 16; o > 0; o >>= 1) var += __shfl_xor_sync(0xffffffffu, var, o);
    float rstd = rsqrtf(var * (1.f/DD) + 1e-5f);
    int c0 = lane*4, c1 = 128 + lane*4;
    float4 g0 = *(const float4*)(g + c0), g1 = *(const float4*)(g + c1);
    float4 b0 = *(const float4*)(b + c0), b1 = *(const float4*)(b + c1);
    float y[8];
    y[0]=(x[0]-mean)*rstd*g0.x+b0.x; y[1]=(x[1]-mean)*rstd*g0.y+b0.y;
    y[2]=(x[2]-mean)*rstd*g0.z+b0.z; y[3]=(x[3]-mean)*rstd*g0.w+b0.w;
    y[4]=(x[4]-mean)*rstd*g1.x+b1.x; y[5]=(x[5]-mean)*rstd*g1.y+b1.y;
    y[6]=(x[6]-mean)*rstd*g1.z+b1.z; y[7]=(x[7]-mean)*rstd*g1.w+b1.w;
    float4* w4 = (float4*)(src + base);
    w4[lane]    = make_float4(y[0],y[1],y[2],y[3]);
    w4[lane+32] = make_float4(y[4],y[5],y[6],y[7]);
    #pragma unroll
    for (int hblk = 0; hblk < 2; hblk++) {
        size_t o = base + (hblk ? (size_t)c1 : (size_t)c0);
        #pragma unroll
        for (int p = 0; p < 2; p++) {
            __half h0,l0,h1,l1;
            split2h(y[hblk*4+2*p],   h0, l0);
            split2h(y[hblk*4+2*p+1], h1, l1);
            __half2 hh; hh.x=h0; hh.y=h1;
            __half2 ll; ll.x=l0; ll.y=l1;
            *(__half2*)(oh + o + 2*p) = hh;
            *(__half2*)(ol + o + 2*p) = ll;
        }
    }
    if (qh) {
        const float4* p4 = (const float4*)(pos + base);
        float4 pa = p4[lane], pb = p4[lane+32];
        float z[8];
        z[0]=y[0]+pa.x; z[1]=y[1]+pa.y; z[2]=y[2]+pa.z; z[3]=y[3]+pa.w;
        z[4]=y[4]+pb.x; z[5]=y[5]+pb.y; z[6]=y[6]+pb.z; z[7]=y[7]+pb.w;
        #pragma unroll
        for (int hblk = 0; hblk < 2; hblk++) {
            size_t o = base + (hblk ? (size_t)c1 : (size_t)c0);
            #pragma unroll
            for (int p = 0; p < 2; p++) {
                __half h0,l0,h1,l1;
                split2h(z[hblk*4+2*p],   h0, l0);
                split2h(z[hblk*4+2*p+1], h1, l1);
                __half2 hh; hh.x=h0; hh.y=h1;
                __half2 ll; ll.x=l0; ll.y=l1;
                *(__half2*)(qh + o + 2*p) = hh;
                *(__half2*)(ql + o + 2*p) = ll;
            }
        }
    }
}

// ---------------- finalize ----------------
__global__ void finalize_kernel(const float* __restrict__ src, float* __restrict__ out, int out_size)
{
    int i = blockIdx.x*blockDim.x + threadIdx.x;
    if (i >= out_size) return;
    const int n = NB*LQT*DD;
    if (i < n) { out[i] = src[i]; return; }
    int j = i - n;
    float v;
    if (j < 4)       v = (float)c_start[j];
    else if (j < 12) v = (float)c_H[(j-4) >> 1];
    else             v = 1.0f;
    out[i] = v;
}

// ---------------- host orchestration ----------------
extern "C" void kernel_launch(void* const* d_in, const int* in_sizes, int n_in,
                              void* d_out, int out_size)
{
    (void)n_in;
    const float *X[4], *FW[4], *FB[4];
    if (in_sizes[1] == 65536) {
        for (int i = 0; i < 4; i++) {
            X[i]  = (const float*)d_in[3*i+0];
            FW[i] = (const float*)d_in[3*i+1];
            FB[i] = (const float*)d_in[3*i+2];
        }
    } else {
        for (int i = 0; i < 4; i++) {
            X[i]  = (const float*)d_in[i];
            FW[i] = (const float*)d_in[4+2*i];
            FB[i] = (const float*)d_in[5+2*i];
        }
    }
    const float* gn_g  = (const float*)d_in[12];
    const float* gn_b  = (const float*)d_in[13];
    const float* lemb  = (const float*)d_in[14];
    const float* off_w = (const float*)d_in[15];
    const float* off_b = (const float*)d_in[16];
    const float* aw_w  = (const float*)d_in[17];
    const float* aw_b  = (const float*)d_in[18];
    const float* val_w = (const float*)d_in[19];
    const float* val_b = (const float*)d_in[20];
    const float* out_w = (const float*)d_in[21];
    const float* out_b = (const float*)d_in[22];
    const float* ln1_g = (const float*)d_in[23];
    const float* ln1_b = (const float*)d_in[24];
    const float* l1_w  = (const float*)d_in[25];
    const float* l1_b  = (const float*)d_in[26];
    const float* l2_w  = (const float*)d_in[27];
    const float* l2_b  = (const float*)d_in[28];
    const float* ln2_g = (const float*)d_in[29];
    const float* ln2_b = (const float*)d_in[30];

    float *src, *pos, *off, *aw, *val, *att, *ref, *cbias;
    __half *wf, *qh, *ql, *sh, *sl, *th, *tl, *msh, *msl, *hbh, *hbl;
    cudaGetSymbolAddress((void**)&src,   g_src);
    cudaGetSymbolAddress((void**)&pos,   g_pos);
    cudaGetSymbolAddress((void**)&off,   g_off);
    cudaGetSymbolAddress((void**)&aw,    g_aw);
    cudaGetSymbolAddress((void**)&val,   g_val);
    cudaGetSymbolAddress((void**)&att,   g_att);
    cudaGetSymbolAddress((void**)&ref,   g_ref);
    cudaGetSymbolAddress((void**)&cbias, g_cbias);
    cudaGetSymbolAddress((void**)&wf,    g_wf);
    cudaGetSymbolAddress((void**)&qh,    g_qh);
    cudaGetSymbolAddress((void**)&ql,    g_ql);
    cudaGetSymbolAddress((void**)&sh,    g_sh);
    cudaGetSymbolAddress((void**)&sl,    g_sl);
    cudaGetSymbolAddress((void**)&th,    g_th);
    cudaGetSymbolAddress((void**)&tl,    g_tl);
    cudaGetSymbolAddress((void**)&msh,   g_msh);
    cudaGetSymbolAddress((void**)&msl,   g_msl);
    cudaGetSymbolAddress((void**)&hbh,   g_hbh);
    cudaGetSymbolAddress((void**)&hbl,   g_hbl);

    cudaFuncSetAttribute(gemm_bb_kernel,
        cudaFuncAttributeMaxDynamicSharedMemorySize, SMEM_BB);

    setup_kernel<<<(N_WB + LQT*DD + 255)/256, 256>>>(
        off_w, aw_w, val_w, out_w, l1_w, l2_w, off_b, aw_b, wf, cbias, lemb, pos, ref);
    tokenizer_kernel<<<1536, 256>>>(X[0], X[1], X[2], X[3],
                                    FW[0], FW[1], FW[2], FW[3],
                                    FB[0], FB[1], FB[2], FB[3], src);
    gn_kernel<<<4*2*32, 256>>>(src, gn_g, gn_b, pos, sh, sl, qh, ql);

    const int GY = (MTOT + 63)/64;  // 383
    dim3 g_oawval(5, GY), g_256(2, GY), g_l1(8, GY);
    const int BIGX = 1 << 20;
    const int MSD_BLK = (NB*LQT*4 + 7)/8;   // 12240

    for (int l = 0; l < NLAY; l++) {
        // merged: oaw GEMM (bx 0..2, from q-split) + val GEMM (bx 3..4, from s-split)
        gemm_bb_kernel<<<g_oawval, 256, SMEM_BB>>>(
            qh, ql, wf + OFF_OAW + (size_t)l*98304, cbias + l*384,
            off, aw, 256, (__half*)0, (__half*)0,
            MTOT, 384, 256, 0, 0,
            3,
            sh, sl, wf + OFF_VAL + (size_t)l*65536, val_b + l*DD,
            val, 256, 1);
        msdeform_kernel<<<MSD_BLK, 256>>>((const __half*)val, off, aw, ref, msh, msl);
        gemm_bb_kernel<<<g_256, 256, SMEM_BB>>>(
            msh, msl, wf + OFF_OUT + (size_t)l*65536, out_b + l*DD,
            att, (float*)0, 256, (__half*)0, (__half*)0,
            MTOT, 256, 256, 0, 0,
            BIGX, (__half*)0, (__half*)0, (__half*)0, (const float*)0, (float*)0, 0, 0);
        addln_kernel<<<MTOT/8, 256>>>(src, att, ln1_g + l*DD, ln1_b + l*DD,
            th, tl, (__half*)0, (__half*)0, (const float*)0);
        gemm_bb_kernel<<<g_l1, 256, SMEM_BB>>>(
            th, tl, wf + OFF_L1 + (size_t)l*262144, l1_b + l*DFF_,
            (float*)0, (float*)0, 1024, hbh, hbl,
            MTOT, 1024, 256, 1, 2,
            BIGX, (__half*)0, (__half*)0, (__half*)0, (const float*)0, (float*)0, 0, 0);
        gemm_bb_kernel<<<g_256, 256, SMEM_BB>>>(
            hbh, hbl, wf + OFF_L2 + (size_t)l*262144, l2_b + l*DD,
            att, (float*)0, 256, (__half*)0, (__half*)0,
            MTOT, 256, 1024, 0, 0,
            BIGX, (__half*)0, (__half*)0, (__half*)0, (const float*)0, (float*)0, 0, 0);
        addln_kernel<<<MTOT/8, 256>>>(src, att, ln2_g + l*DD, ln2_b + l*DD,
            sh, sl, qh, ql, pos);
    }

    finalize_kernel<<<(out_size + 255)/256, 256>>>(src, (float*)d_out, out_size);
}